// round 14
// baseline (speedup 1.0000x reference)
#include <cuda_runtime.h>
#include <cuda_bf16.h>
#include <cstdint>

#define BATCH 4
#define NSEQ  4096
#define DIM   512
#define ABS   64
#define NT    64          // tiles of 64 rows per batch (NSEQ/ABS)
#define MTOT  (BATCH * NSEQ)

// planar split-bf16 geometry: 2 planes (hi @0..15, lo @16..31); row stride
// 40 bf16 = 20 u32 = 80 B (LDSM conflict-free: 20*l mod 32 is a permutation)
#define RSTRE 40
#define RSTRW 20

// -------- scratch (device globals; no runtime allocation) --------
__device__ float g_inv[MTOT];                    // per-row inverse L2 norms
__device__ float g_S0[BATCH * NT * ABS * DIM];   // exclusive tile-prefix sums of c (32 MB)
__device__ float g_Wc[ABS * DIM];                // W_abs @ W_merge[512:1024]
// pre-converted A operand image: [36 ch][16384 m][40] bf16 (47 MB)
//   ch 0..31  = raw data chunks   (written by k_norms)
//   ch 32..35 = pooled chunks     (written by k_pooled epilogue)
__device__ __align__(16) __nv_bfloat16 g_Ap[36 * MTOT * RSTRE];
// pre-converted B operand: [4 nb][36 ch][128 n][40] bf16 (~1.5 MB)
__device__ __align__(16) __nv_bfloat16 g_Bp[4 * 36 * 128 * RSTRE];

// -------- helpers --------
__device__ __forceinline__ uint32_t pack2(__nv_bfloat16 a, __nv_bfloat16 b) {
    return (uint32_t)__bfloat16_as_ushort(a) | ((uint32_t)__bfloat16_as_ushort(b) << 16);
}
__device__ __forceinline__ void split2(float2 v, uint32_t& hh, uint32_t& ll) {
    __nv_bfloat16 h0 = __float2bfloat16(v.x);
    __nv_bfloat16 h1 = __float2bfloat16(v.y);
    __nv_bfloat16 l0 = __float2bfloat16(v.x - __bfloat162float(h0));
    __nv_bfloat16 l1 = __float2bfloat16(v.y - __bfloat162float(h1));
    hh = pack2(h0, h1); ll = pack2(l0, l1);
}
__device__ __forceinline__ void mma_bf16(float* d, const uint32_t* a, const uint32_t* b) {
    asm volatile(
        "mma.sync.aligned.m16n8k16.row.col.f32.bf16.bf16.f32 "
        "{%0,%1,%2,%3}, {%4,%5,%6,%7}, {%8,%9}, {%0,%1,%2,%3};\n"
        : "+f"(d[0]), "+f"(d[1]), "+f"(d[2]), "+f"(d[3])
        : "r"(a[0]), "r"(a[1]), "r"(a[2]), "r"(a[3]), "r"(b[0]), "r"(b[1]));
}
__device__ __forceinline__ void ldsm4(uint32_t* q, uint32_t addr) {
    asm volatile("ldmatrix.sync.aligned.m8n8.x4.shared.b16 {%0,%1,%2,%3}, [%4];"
                 : "=r"(q[0]), "=r"(q[1]), "=r"(q[2]), "=r"(q[3]) : "r"(addr));
}
__device__ __forceinline__ uint32_t smem_u32(const void* p) {
    uint32_t a;
    asm("{ .reg .u64 t; cvta.to.shared.u64 t, %1; cvt.u32.u64 %0, t; }" : "=r"(a) : "l"(p));
    return a;
}

// ============================================================
// Kernel A: per-row inverse L2 norm AND raw-data split-bf16 image.
// Block = 8 rows. Phase 1: compute + stage split planes in smem.
// Phase 2: write g_Ap chunks 0..31 as contiguous 640B runs (coalesced).
// ============================================================
__global__ void __launch_bounds__(256) k_norms(const float* __restrict__ data) {
    __shared__ uint32_t sm[8 * 32 * 21];   // [r][ch][21 u32] (pad 21 vs 20)

    int m0 = blockIdx.x * 8;
    int w = threadIdx.x >> 5, lane = threadIdx.x & 31;
    int row = m0 + w;

    const float4* src = (const float4*)(data + (size_t)row * DIM);
    float4 v[4];
    float s = 0.f;
    #pragma unroll
    for (int j = 0; j < 4; ++j) {
        v[j] = src[lane + 32 * j];
        s += v[j].x * v[j].x + v[j].y * v[j].y + v[j].z * v[j].z + v[j].w * v[j].w;
    }
    #pragma unroll
    for (int off = 16; off > 0; off >>= 1)
        s += __shfl_xor_sync(0xFFFFFFFFu, s, off);
    if (lane == 0) g_inv[row] = rsqrtf(fmaxf(s, 1e-12f));

    // stage split planes: hi at slots 0..7, lo at 8..15 of each [r][ch] row
    #pragma unroll
    for (int j = 0; j < 4; ++j) {
        int d4 = lane + 32 * j;        // 0..127
        int ch = d4 >> 2;              // chunk 0..31
        int k2 = (d4 & 3) * 2;         // 0,2,4,6
        uint32_t h0, l0, h1, l1;
        split2(make_float2(v[j].x, v[j].y), h0, l0);
        split2(make_float2(v[j].z, v[j].w), h1, l1);
        uint32_t* p = &sm[(w * 32 + ch) * 21 + k2];
        p[0] = h0; p[1] = h1; p[8] = l0; p[9] = l1;
    }
    __syncthreads();

    // write out: for each ch, 8 rows x 20 u32 = 640 B contiguous
    uint32_t* ApW = (uint32_t*)g_Ap;
    #pragma unroll
    for (int i = 0; i < 20; ++i) {
        int f = threadIdx.x + 256 * i;     // 0..5119
        int ch = f / 160;
        int rem = f - ch * 160;
        int r = rem / 20;
        int k = rem - r * 20;
        ApW[((size_t)ch * MTOT + m0 + r) * RSTRW + k] = sm[(r * 32 + ch) * 21 + k];
    }
}

// ============================================================
// Kernel B: exclusive tile-prefix scan of normalized rows.
// Loads batched 8 ahead before stores -> MLP=8.
// ============================================================
__global__ void k_scan(const float* __restrict__ data) {
    int idx = blockIdx.x * blockDim.x + threadIdx.x;   // 0..32767
    int b  = idx >> 13;
    int r  = idx & 8191;
    int a  = r >> 7;             // residue class 0..63
    int d4 = r & 127;            // float4 index within DIM

    const float4* df = (const float4*)data;
    float4*       sf = (float4*)g_S0;

    float4 acc = make_float4(0.f, 0.f, 0.f, 0.f);
    for (int g0 = 0; g0 < NT; g0 += 8) {
        float4 v[8]; float iv[8];
        #pragma unroll
        for (int j = 0; j < 8; ++j) {
            int row = b * NSEQ + (g0 + j) * ABS + a;
            iv[j] = __ldg(&g_inv[row]);
            v[j]  = df[(size_t)row * 128 + d4];
        }
        #pragma unroll
        for (int j = 0; j < 8; ++j) {
            size_t si = ((size_t)((b * NT + g0 + j) * ABS + a)) * 128 + d4;
            sf[si] = acc;                               // exclusive
            acc.x += v[j].x * iv[j]; acc.y += v[j].y * iv[j];
            acc.z += v[j].z * iv[j]; acc.w += v[j].w * iv[j];
        }
    }
}

// ============================================================
// Kernel Wc: W_comb = W_abs @ W_merge[512:1024]
// ============================================================
__global__ void k_wc(const float* __restrict__ Wabs, const float* __restrict__ Wm) {
    int idx = blockIdx.x * blockDim.x + threadIdx.x;
    int a = idx >> 9;
    int dout = idx & 511;
    float acc = 0.f;
    #pragma unroll 8
    for (int k = 0; k < DIM; ++k)
        acc = fmaf(Wabs[a * DIM + k], Wm[(size_t)(DIM + k) * DIM + dout], acc);
    g_Wc[idx] = acc;
}

// ============================================================
// Kernel prepB: pre-convert GEMM B operand into 2-plane split-bf16
// [nb 4][ch 36][n 128][40]: elems 0..15 = hi, 16..31 = lo
// ============================================================
__global__ void k_prepB(const float* __restrict__ Wm) {
    int idx = blockIdx.x * blockDim.x + threadIdx.x;   // 0..294911
    int k   = idx & 15;
    int n   = (idx >> 4) & 127;
    int rest = idx >> 11;            // 0..143
    int ch  = rest % 36;
    int nb  = rest / 36;             // 0..3

    float v;
    if (ch < 32) v = Wm[(size_t)(ch * 16 + k) * DIM + nb * 128 + n];
    else         v = g_Wc[(size_t)((ch - 32) * 16 + k) * DIM + nb * 128 + n];

    __nv_bfloat16 h = __float2bfloat16(v);
    __nv_bfloat16 l = __float2bfloat16(v - __bfloat162float(h));
    __nv_bfloat16* p = &g_Bp[((size_t)(nb * 36 + ch) * 128 + n) * RSTRE + k];
    p[0]  = h;   // hi plane
    p[16] = l;   // lo plane
}

// ============================================================
// Kernel C: pooled via mma.sync + ldmatrix, double-buffered smem.
// One CTA per (b,t): P[64x128] = c_tile[64x512] @ [S0_tile ; c_tile]^T
// Epilogue writes split-bf16 DIRECTLY into g_Ap chunks 32..35.
// ============================================================
__device__ __forceinline__ void pooled_fill(
    uint32_t* AsW, uint32_t* BsW,
    const float* cbase, const float* sbase, const float* ivs,
    int kc0, int tid)
{
    #pragma unroll
    for (int jj = 0; jj < 2; ++jj) {
        int f = tid + 256 * jj;        // 0..511
        int k2 = f & 7, m = f >> 3;
        float2 v = *(const float2*)(sbase + (size_t)m * DIM + kc0 + 2 * k2);
        uint32_t hh, ll; split2(v, hh, ll);
        uint32_t* p = &BsW[m * RSTRW + k2];
        p[0] = hh; p[8] = ll;
    }
    #pragma unroll
    for (int jj = 0; jj < 2; ++jj) {
        int f = tid + 256 * jj;
        int k2 = f & 7, m = f >> 3;
        float2 v = *(const float2*)(cbase + (size_t)m * DIM + kc0 + 2 * k2);
        float iv = ivs[m];
        v.x *= iv; v.y *= iv;
        uint32_t hh, ll; split2(v, hh, ll);
        uint32_t* pa = &AsW[m * RSTRW + k2];
        pa[0] = hh; pa[8] = ll;
        uint32_t* pb = &BsW[(64 + m) * RSTRW + k2];
        pb[0] = hh; pb[8] = ll;
    }
}

__global__ void __launch_bounds__(256) k_pooled(const float* __restrict__ data) {
    __shared__ uint32_t AsW[2][64 * RSTRW];    // c as A   (2 x 5 KB)
    __shared__ uint32_t BsW[2][128 * RSTRW];   // [S0 ; c] as B (2 x 10 KB)
    __shared__ float    ivs[64];

    int bt = blockIdx.x;
    int b = bt >> 6, t = bt & 63;
    const float* cbase = data + ((size_t)b * NSEQ + t * ABS) * DIM;
    const float* sbase = g_S0 + ((size_t)(b * NT + t)) * ABS * DIM;

    int tid = threadIdx.x;
    int wid = tid >> 5, lane = tid & 31;
    int gr = lane >> 2, tq = lane & 3;
    int warp_m = wid & 1, warp_n = wid >> 1;   // 2 x 4

    if (tid < 64) ivs[tid] = g_inv[b * NSEQ + t * ABS + tid];
    __syncthreads();

    // LDSM per-lane byte offsets (relative to stage base)
    int mat = lane >> 3, mr = lane & 7;
    uint32_t aoff = ((uint32_t)(warp_m * 32 + (mat & 1) * 8 + mr) * RSTRE + (mat >> 1) * 8) * 2;
    uint32_t boff = ((uint32_t)(warp_n * 16 + (mat & 1) * 8 + mr) * RSTRE + (mat >> 1) * 8) * 2;
    uint32_t asb[2] = { smem_u32(AsW[0]), smem_u32(AsW[1]) };
    uint32_t bsb[2] = { smem_u32(BsW[0]), smem_u32(BsW[1]) };

    float acc_h[2][2][4], acc_d[2][2][4];
    #pragma unroll
    for (int mt = 0; mt < 2; ++mt)
        #pragma unroll
        for (int nt = 0; nt < 2; ++nt)
            #pragma unroll
            for (int c = 0; c < 4; ++c) { acc_h[mt][nt][c] = 0.f; acc_d[mt][nt][c] = 0.f; }

    pooled_fill(AsW[0], BsW[0], cbase, sbase, ivs, 0, tid);
    __syncthreads();

    for (int ch = 0; ch < 32; ++ch) {
        int cur = ch & 1;
        if (ch + 1 < 32)
            pooled_fill(AsW[cur ^ 1], BsW[cur ^ 1], cbase, sbase, ivs, (ch + 1) * 16, tid);

        #pragma unroll
        for (int ks = 0; ks < 3; ++ks) {
            uint32_t ka2 = (ks == 2) ? 32u : 0u;   // bytes (16 elems)
            uint32_t kb2 = (ks == 1) ? 32u : 0u;
            uint32_t bh[4], bd[4];
            ldsm4(bh, bsb[cur] + boff + kb2);                       // S0 rows
            ldsm4(bd, bsb[cur] + boff + 64 * RSTRE * 2 + kb2);      // c rows
            uint32_t bhf[2][2] = { { bh[0], bh[2] }, { bh[1], bh[3] } };
            uint32_t bdf[2][2] = { { bd[0], bd[2] }, { bd[1], bd[3] } };
            #pragma unroll
            for (int mt = 0; mt < 2; ++mt) {
                uint32_t aq[4];
                ldsm4(aq, asb[cur] + aoff + ka2 + (uint32_t)(mt * 16 * RSTRE * 2));
                #pragma unroll
                for (int nt = 0; nt < 2; ++nt) {
                    mma_bf16(acc_h[mt][nt], aq, bhf[nt]);
                    mma_bf16(acc_d[mt][nt], aq, bdf[nt]);
                }
            }
        }
        __syncthreads();
    }

    // epilogue: combine + causal mask + 1/64, write split-bf16 into g_Ap ch 32+warp_n
    const float scale = 1.0f / 64.0f;
    uint32_t* ApW = (uint32_t*)g_Ap;
    int mgbase = b * NSEQ + t * ABS;
    int ch = 32 + warp_n;
    #pragma unroll
    for (int mt = 0; mt < 2; ++mt) {
        #pragma unroll
        for (int half = 0; half < 2; ++half) {
            int i = warp_m * 32 + mt * 16 + gr + half * 8;
            #pragma unroll
            for (int nt = 0; nt < 2; ++nt) {
                int j = warp_n * 16 + nt * 8 + 2 * tq;
                float v0 = acc_h[mt][nt][half * 2 + 0] + ((j     <= i) ? acc_d[mt][nt][half * 2 + 0] : 0.f);
                float v1 = acc_h[mt][nt][half * 2 + 1] + ((j + 1 <= i) ? acc_d[mt][nt][half * 2 + 1] : 0.f);
                uint32_t hh, ll;
                split2(make_float2(v0 * scale, v1 * scale), hh, ll);
                int k2 = nt * 4 + tq;
                uint32_t* p = ApW + ((size_t)ch * MTOT + mgbase + i) * RSTRW + k2;
                p[0] = hh; p[8] = ll;
            }
        }
    }
}

// ============================================================
// Kernel D: merged = data @ W1 + pooled @ W_comb via bf16 split MMA.
// CTA tile 128m x 128n -> grid (4, 128) = 512 CTAs.
// Fills are RAW coalesced uint4 copies (A contiguous per chunk in g_Ap).
// ldmatrix fragment loads; 36-chunk double-buffered pipeline.
// ============================================================
__device__ __forceinline__ void gemm_fill(
    uint32_t* AsW, uint32_t* BsW, int m0, int nb, int ch36, int tid)
{
    // A: chunk ch36, rows m0..m0+128 = 2560 u32 contiguous
    const uint4* asrc = (const uint4*)((const uint32_t*)g_Ap + ((size_t)ch36 * MTOT + m0) * RSTRW);
    uint4* adst = (uint4*)AsW;
    #pragma unroll
    for (int jj = 0; jj < 3; ++jj) {
        int f = tid + 256 * jj;        // need 640
        if (f < 640) adst[f] = asrc[f];
    }
    // B: 128 n rows x 20 u32 contiguous
    const uint4* bsrc = (const uint4*)&g_Bp[(size_t)(nb * 36 + ch36) * 128 * RSTRE];
    uint4* bdst = (uint4*)BsW;
    #pragma unroll
    for (int jj = 0; jj < 3; ++jj) {
        int f = tid + 256 * jj;        // need 640
        if (f < 640) bdst[f] = bsrc[f];
    }
}

__global__ void __launch_bounds__(256) k_gemm_mma(float* __restrict__ out) {
    __shared__ uint32_t AsW[2][128 * RSTRW];   // 2 x 10 KB
    __shared__ uint32_t BsW[2][128 * RSTRW];   // 2 x 10 KB

    int tid = threadIdx.x;
    int wid = tid >> 5, lane = tid & 31;
    int gr = lane >> 2, tq = lane & 3;
    int warp_m = wid & 1, warp_n = wid >> 1;   // 2 x 4
    int m0 = blockIdx.y * 128, nb = blockIdx.x;
    int n0 = nb * 128;

    // LDSM per-lane byte offsets
    int mat = lane >> 3, mr = lane & 7;
    uint32_t aoff = ((uint32_t)(warp_m * 64 + (mat & 1) * 8 + mr) * RSTRE + (mat >> 1) * 8) * 2;
    uint32_t boff = ((uint32_t)(warp_n * 32 + (mat & 1) * 8 + mr) * RSTRE + (mat >> 1) * 8) * 2;
    uint32_t asb[2] = { smem_u32(AsW[0]), smem_u32(AsW[1]) };
    uint32_t bsb[2] = { smem_u32(BsW[0]), smem_u32(BsW[1]) };

    float acc[4][4][4];
    #pragma unroll
    for (int mt = 0; mt < 4; ++mt)
        #pragma unroll
        for (int nt = 0; nt < 4; ++nt)
            #pragma unroll
            for (int c = 0; c < 4; ++c) acc[mt][nt][c] = 0.f;

    gemm_fill(AsW[0], BsW[0], m0, nb, 0, tid);
    __syncthreads();

    for (int ch = 0; ch < 36; ++ch) {
        int cur = ch & 1;
        if (ch + 1 < 36)
            gemm_fill(AsW[cur ^ 1], BsW[cur ^ 1], m0, nb, ch + 1, tid);

        #pragma unroll
        for (int ks = 0; ks < 3; ++ks) {
            uint32_t ka2 = (ks == 2) ? 32u : 0u;
            uint32_t kb2 = (ks == 1) ? 32u : 0u;
            uint32_t bq0[4], bq1[4];
            ldsm4(bq0, bsb[cur] + boff + kb2);                         // cols +0..15
            ldsm4(bq1, bsb[cur] + boff + 16 * RSTRE * 2 + kb2);        // cols +16..31
            uint32_t bf[4][2] = { { bq0[0], bq0[2] }, { bq0[1], bq0[3] },
                                  { bq1[0], bq1[2] }, { bq1[1], bq1[3] } };
            #pragma unroll
            for (int mt = 0; mt < 4; ++mt) {
                uint32_t aq[4];
                ldsm4(aq, asb[cur] + aoff + ka2 + (uint32_t)(mt * 16 * RSTRE * 2));
                #pragma unroll
                for (int nt = 0; nt < 4; ++nt)
                    mma_bf16(acc[mt][nt], aq, bf[nt]);
            }
        }
        __syncthreads();
    }

    // ---- epilogue ----
    #pragma unroll
    for (int mt = 0; mt < 4; ++mt) {
        int r = m0 + warp_m * 64 + mt * 16 + gr;
        #pragma unroll
        for (int nt = 0; nt < 4; ++nt) {
            int c = n0 + warp_n * 32 + nt * 8 + 2 * tq;
            *(float2*)&out[(size_t)r * DIM + c]       = make_float2(acc[mt][nt][0], acc[mt][nt][1]);
            *(float2*)&out[(size_t)(r + 8) * DIM + c] = make_float2(acc[mt][nt][2], acc[mt][nt][3]);
        }
    }
}

// ============================================================
extern "C" void kernel_launch(void* const* d_in, const int* in_sizes, int n_in,
                              void* d_out, int out_size) {
    const float* data = (const float*)d_in[0];   // [4,4096,512]
    const float* Wabs = (const float*)d_in[1];   // [64,512]
    const float* Wm   = (const float*)d_in[2];   // [1024,512]
    float* out = (float*)d_out;                  // [4,4096,512]

    k_norms<<<2048, 256>>>(data);                // inv norms + A image ch 0..31
    k_wc<<<128, 256>>>(Wabs, Wm);
    k_prepB<<<1152, 256>>>(Wm);
    k_scan<<<256, 128>>>(data);
    k_pooled<<<BATCH * NT, 256>>>(data);         // writes A image ch 32..35
    k_gemm_mma<<<dim3(4, 128), 256>>>(out);
}

// round 15
// speedup vs baseline: 1.0740x; 1.0740x over previous
#include <cuda_runtime.h>
#include <cuda_bf16.h>
#include <cstdint>

#define BATCH 4
#define NSEQ  4096
#define DIM   512
#define ABS   64
#define NT    64          // tiles of 64 rows per batch (NSEQ/ABS)
#define MTOT  (BATCH * NSEQ)

// planar split-bf16 smem geometry: 2 planes (hi @0..15, lo @16..31); row stride
// 40 bf16 = 20 u32 = 80 B (LDSM conflict-free: 20*l mod 32 is a permutation)
#define RSTRE 40
#define RSTRW 20

// -------- scratch (device globals; no runtime allocation) --------
__device__ float g_inv[MTOT];                    // per-row inverse L2 norms
__device__ float g_S0[BATCH * NT * ABS * DIM];   // exclusive tile-prefix sums of c (32 MB)
__device__ float g_pooled[MTOT * ABS];           // [B,N,64] fp32 (4 MB)
__device__ float g_Wc[ABS * DIM];                // W_abs @ W_merge[512:1024]
// pre-converted B operand: [4 nb][36 ch][128 n][40] bf16 (~1.5 MB)
__device__ __align__(16) __nv_bfloat16 g_Bp[4 * 36 * 128 * RSTRE];

// -------- helpers --------
__device__ __forceinline__ uint32_t pack2(__nv_bfloat16 a, __nv_bfloat16 b) {
    return (uint32_t)__bfloat16_as_ushort(a) | ((uint32_t)__bfloat16_as_ushort(b) << 16);
}
__device__ __forceinline__ void split2(float2 v, uint32_t& hh, uint32_t& ll) {
    __nv_bfloat16 h0 = __float2bfloat16(v.x);
    __nv_bfloat16 h1 = __float2bfloat16(v.y);
    __nv_bfloat16 l0 = __float2bfloat16(v.x - __bfloat162float(h0));
    __nv_bfloat16 l1 = __float2bfloat16(v.y - __bfloat162float(h1));
    hh = pack2(h0, h1); ll = pack2(l0, l1);
}
__device__ __forceinline__ void mma_bf16(float* d, const uint32_t* a, const uint32_t* b) {
    asm volatile(
        "mma.sync.aligned.m16n8k16.row.col.f32.bf16.bf16.f32 "
        "{%0,%1,%2,%3}, {%4,%5,%6,%7}, {%8,%9}, {%0,%1,%2,%3};\n"
        : "+f"(d[0]), "+f"(d[1]), "+f"(d[2]), "+f"(d[3])
        : "r"(a[0]), "r"(a[1]), "r"(a[2]), "r"(a[3]), "r"(b[0]), "r"(b[1]));
}
__device__ __forceinline__ void ldsm4(uint32_t* q, uint32_t addr) {
    asm volatile("ldmatrix.sync.aligned.m8n8.x4.shared.b16 {%0,%1,%2,%3}, [%4];"
                 : "=r"(q[0]), "=r"(q[1]), "=r"(q[2]), "=r"(q[3]) : "r"(addr));
}
__device__ __forceinline__ uint32_t smem_u32(const void* p) {
    uint32_t a;
    asm("{ .reg .u64 t; cvta.to.shared.u64 t, %1; cvt.u32.u64 %0, t; }" : "=r"(a) : "l"(p));
    return a;
}

// ============================================================
// Kernel A: per-row inverse L2 norm (one warp per row) — light
// ============================================================
__global__ void k_norms(const float* __restrict__ data) {
    int gw   = (blockIdx.x * blockDim.x + threadIdx.x) >> 5;
    int lane = threadIdx.x & 31;
    const float4* src = (const float4*)(data + (size_t)gw * DIM);
    float s = 0.f;
    #pragma unroll
    for (int j = 0; j < 4; ++j) {
        float4 v = src[lane + 32 * j];
        s += v.x * v.x + v.y * v.y + v.z * v.z + v.w * v.w;
    }
    #pragma unroll
    for (int off = 16; off > 0; off >>= 1)
        s += __shfl_xor_sync(0xFFFFFFFFu, s, off);
    if (lane == 0) g_inv[gw] = rsqrtf(fmaxf(s, 1e-12f));
}

// ============================================================
// Kernel B: exclusive tile-prefix scan of normalized rows.
// Loads batched 8 ahead before stores -> MLP=8 (verified 36->24us).
// ============================================================
__global__ void k_scan(const float* __restrict__ data) {
    int idx = blockIdx.x * blockDim.x + threadIdx.x;   // 0..32767
    int b  = idx >> 13;
    int r  = idx & 8191;
    int a  = r >> 7;             // residue class 0..63
    int d4 = r & 127;            // float4 index within DIM

    const float4* df = (const float4*)data;
    float4*       sf = (float4*)g_S0;

    float4 acc = make_float4(0.f, 0.f, 0.f, 0.f);
    for (int g0 = 0; g0 < NT; g0 += 8) {
        float4 v[8]; float iv[8];
        #pragma unroll
        for (int j = 0; j < 8; ++j) {
            int row = b * NSEQ + (g0 + j) * ABS + a;
            iv[j] = __ldg(&g_inv[row]);
            v[j]  = df[(size_t)row * 128 + d4];
        }
        #pragma unroll
        for (int j = 0; j < 8; ++j) {
            size_t si = ((size_t)((b * NT + g0 + j) * ABS + a)) * 128 + d4;
            sf[si] = acc;                               // exclusive
            acc.x += v[j].x * iv[j]; acc.y += v[j].y * iv[j];
            acc.z += v[j].z * iv[j]; acc.w += v[j].w * iv[j];
        }
    }
}

// ============================================================
// Kernel Wc: W_comb = W_abs @ W_merge[512:1024]
// ============================================================
__global__ void k_wc(const float* __restrict__ Wabs, const float* __restrict__ Wm) {
    int idx = blockIdx.x * blockDim.x + threadIdx.x;
    int a = idx >> 9;
    int dout = idx & 511;
    float acc = 0.f;
    #pragma unroll 8
    for (int k = 0; k < DIM; ++k)
        acc = fmaf(Wabs[a * DIM + k], Wm[(size_t)(DIM + k) * DIM + dout], acc);
    g_Wc[idx] = acc;
}

// ============================================================
// Kernel prepB: pre-convert GEMM B operand into 2-plane split-bf16
// [nb 4][ch 36][n 128][40]: elems 0..15 = hi, 16..31 = lo
// ============================================================
__global__ void k_prepB(const float* __restrict__ Wm) {
    int idx = blockIdx.x * blockDim.x + threadIdx.x;   // 0..294911
    int k   = idx & 15;
    int n   = (idx >> 4) & 127;
    int rest = idx >> 11;            // 0..143
    int ch  = rest % 36;
    int nb  = rest / 36;             // 0..3

    float v;
    if (ch < 32) v = Wm[(size_t)(ch * 16 + k) * DIM + nb * 128 + n];
    else         v = g_Wc[(size_t)((ch - 32) * 16 + k) * DIM + nb * 128 + n];

    __nv_bfloat16 h = __float2bfloat16(v);
    __nv_bfloat16 l = __float2bfloat16(v - __bfloat162float(h));
    __nv_bfloat16* p = &g_Bp[((size_t)(nb * 36 + ch) * 128 + n) * RSTRE + k];
    p[0]  = h;   // hi plane
    p[16] = l;   // lo plane
}

// ============================================================
// Kernel C: pooled via mma.sync + ldmatrix, double-buffered smem.
// One CTA per (b,t): P[64x128] = c_tile[64x512] @ [S0_tile ; c_tile]^T
// Epilogue writes g_pooled fp32 (R7 architecture).
// ============================================================
__device__ __forceinline__ void pooled_fill(
    uint32_t* AsW, uint32_t* BsW,
    const float* cbase, const float* sbase, const float* ivs,
    int kc0, int tid)
{
    #pragma unroll
    for (int jj = 0; jj < 2; ++jj) {
        int f = tid + 256 * jj;        // 0..511
        int k2 = f & 7, m = f >> 3;
        float2 v = *(const float2*)(sbase + (size_t)m * DIM + kc0 + 2 * k2);
        uint32_t hh, ll; split2(v, hh, ll);
        uint32_t* p = &BsW[m * RSTRW + k2];
        p[0] = hh; p[8] = ll;
    }
    #pragma unroll
    for (int jj = 0; jj < 2; ++jj) {
        int f = tid + 256 * jj;
        int k2 = f & 7, m = f >> 3;
        float2 v = *(const float2*)(cbase + (size_t)m * DIM + kc0 + 2 * k2);
        float iv = ivs[m];
        v.x *= iv; v.y *= iv;
        uint32_t hh, ll; split2(v, hh, ll);
        uint32_t* pa = &AsW[m * RSTRW + k2];
        pa[0] = hh; pa[8] = ll;
        uint32_t* pb = &BsW[(64 + m) * RSTRW + k2];
        pb[0] = hh; pb[8] = ll;
    }
}

__global__ void __launch_bounds__(256) k_pooled(const float* __restrict__ data) {
    __shared__ uint32_t AsW[2][64 * RSTRW];    // c as A   (2 x 5 KB)
    __shared__ uint32_t BsW[2][128 * RSTRW];   // [S0 ; c] as B (2 x 10 KB)
    __shared__ float    ivs[64];

    int bt = blockIdx.x;
    int b = bt >> 6, t = bt & 63;
    const float* cbase = data + ((size_t)b * NSEQ + t * ABS) * DIM;
    const float* sbase = g_S0 + ((size_t)(b * NT + t)) * ABS * DIM;

    int tid = threadIdx.x;
    int wid = tid >> 5, lane = tid & 31;
    int gr = lane >> 2, tq = lane & 3;
    int warp_m = wid & 1, warp_n = wid >> 1;   // 2 x 4

    if (tid < 64) ivs[tid] = g_inv[b * NSEQ + t * ABS + tid];
    __syncthreads();

    // LDSM per-lane byte offsets (relative to stage base)
    int mat = lane >> 3, mr = lane & 7;
    uint32_t aoff = ((uint32_t)(warp_m * 32 + (mat & 1) * 8 + mr) * RSTRE + (mat >> 1) * 8) * 2;
    uint32_t boff = ((uint32_t)(warp_n * 16 + (mat & 1) * 8 + mr) * RSTRE + (mat >> 1) * 8) * 2;
    uint32_t asb[2] = { smem_u32(AsW[0]), smem_u32(AsW[1]) };
    uint32_t bsb[2] = { smem_u32(BsW[0]), smem_u32(BsW[1]) };

    float acc_h[2][2][4], acc_d[2][2][4];
    #pragma unroll
    for (int mt = 0; mt < 2; ++mt)
        #pragma unroll
        for (int nt = 0; nt < 2; ++nt)
            #pragma unroll
            for (int c = 0; c < 4; ++c) { acc_h[mt][nt][c] = 0.f; acc_d[mt][nt][c] = 0.f; }

    pooled_fill(AsW[0], BsW[0], cbase, sbase, ivs, 0, tid);
    __syncthreads();

    for (int ch = 0; ch < 32; ++ch) {
        int cur = ch & 1;
        if (ch + 1 < 32)
            pooled_fill(AsW[cur ^ 1], BsW[cur ^ 1], cbase, sbase, ivs, (ch + 1) * 16, tid);

        #pragma unroll
        for (int ks = 0; ks < 3; ++ks) {
            uint32_t ka2 = (ks == 2) ? 32u : 0u;   // bytes (16 elems)
            uint32_t kb2 = (ks == 1) ? 32u : 0u;
            uint32_t bh[4], bd[4];
            ldsm4(bh, bsb[cur] + boff + kb2);                       // S0 rows
            ldsm4(bd, bsb[cur] + boff + 64 * RSTRE * 2 + kb2);      // c rows
            uint32_t bhf[2][2] = { { bh[0], bh[2] }, { bh[1], bh[3] } };
            uint32_t bdf[2][2] = { { bd[0], bd[2] }, { bd[1], bd[3] } };
            #pragma unroll
            for (int mt = 0; mt < 2; ++mt) {
                uint32_t aq[4];
                ldsm4(aq, asb[cur] + aoff + ka2 + (uint32_t)(mt * 16 * RSTRE * 2));
                #pragma unroll
                for (int nt = 0; nt < 2; ++nt) {
                    mma_bf16(acc_h[mt][nt], aq, bhf[nt]);
                    mma_bf16(acc_d[mt][nt], aq, bdf[nt]);
                }
            }
        }
        __syncthreads();
    }

    const float scale = 1.0f / 64.0f;
    float* obase = g_pooled + ((size_t)b * NSEQ + t * ABS) * ABS;
    #pragma unroll
    for (int mt = 0; mt < 2; ++mt) {
        #pragma unroll
        for (int half = 0; half < 2; ++half) {
            int i = warp_m * 32 + mt * 16 + gr + half * 8;
            #pragma unroll
            for (int nt = 0; nt < 2; ++nt) {
                int j = warp_n * 16 + nt * 8 + 2 * tq;
                float v0 = acc_h[mt][nt][half * 2 + 0] + ((j     <= i) ? acc_d[mt][nt][half * 2 + 0] : 0.f);
                float v1 = acc_h[mt][nt][half * 2 + 1] + ((j + 1 <= i) ? acc_d[mt][nt][half * 2 + 1] : 0.f);
                *(float2*)&obase[(size_t)i * ABS + j] = make_float2(v0 * scale, v1 * scale);
            }
        }
    }
}

// ============================================================
// Kernel D: merged = data @ W1 + pooled @ W_comb via bf16 split MMA.
// CTA tile 128m x 128n -> grid (4, 128) = 512 CTAs (R7 architecture).
// A converted in-kernel (overlaps MMA under double-buffering);
// B copied raw from g_Bp.  ldmatrix fragment loads.
// ============================================================
__device__ __forceinline__ void gemm_fill(
    uint32_t* AsW, uint32_t* BsW,
    const float* __restrict__ data, int m0, int nb, int ch36, int tid)
{
    const float* Ap; int lda, kc0;
    if (ch36 < 32) { Ap = data + (size_t)m0 * DIM;     lda = DIM; kc0 = ch36 * 16; }
    else           { Ap = g_pooled + (size_t)m0 * ABS; lda = ABS; kc0 = (ch36 - 32) * 16; }

    #pragma unroll
    for (int jj = 0; jj < 4; ++jj) {
        int f = tid + 256 * jj;        // 0..1023
        int k2 = f & 7, m = f >> 3;
        float2 v = *(const float2*)(Ap + (size_t)m * lda + kc0 + 2 * k2);
        uint32_t hh, ll; split2(v, hh, ll);
        uint32_t* p = &AsW[m * RSTRW + k2];
        p[0] = hh; p[8] = ll;
    }
    const uint4* bsrc = (const uint4*)&g_Bp[(size_t)(nb * 36 + ch36) * 128 * RSTRE];
    uint4* bdst = (uint4*)BsW;
    #pragma unroll
    for (int jj = 0; jj < 3; ++jj) {
        int f = tid + 256 * jj;        // need 640 (= 128*20/4)
        if (f < 640) bdst[f] = bsrc[f];
    }
}

__global__ void __launch_bounds__(256) k_gemm_mma(const float* __restrict__ data,
                                                 float* __restrict__ out) {
    __shared__ uint32_t AsW[2][128 * RSTRW];   // 2 x 10 KB
    __shared__ uint32_t BsW[2][128 * RSTRW];   // 2 x 10 KB

    int tid = threadIdx.x;
    int wid = tid >> 5, lane = tid & 31;
    int gr = lane >> 2, tq = lane & 3;
    int warp_m = wid & 1, warp_n = wid >> 1;   // 2 x 4
    int m0 = blockIdx.y * 128, nb = blockIdx.x;
    int n0 = nb * 128;

    // LDSM per-lane byte offsets
    int mat = lane >> 3, mr = lane & 7;
    uint32_t aoff = ((uint32_t)(warp_m * 64 + (mat & 1) * 8 + mr) * RSTRE + (mat >> 1) * 8) * 2;
    uint32_t boff = ((uint32_t)(warp_n * 32 + (mat & 1) * 8 + mr) * RSTRE + (mat >> 1) * 8) * 2;
    uint32_t asb[2] = { smem_u32(AsW[0]), smem_u32(AsW[1]) };
    uint32_t bsb[2] = { smem_u32(BsW[0]), smem_u32(BsW[1]) };

    float acc[4][4][4];
    #pragma unroll
    for (int mt = 0; mt < 4; ++mt)
        #pragma unroll
        for (int nt = 0; nt < 4; ++nt)
            #pragma unroll
            for (int c = 0; c < 4; ++c) acc[mt][nt][c] = 0.f;

    gemm_fill(AsW[0], BsW[0], data, m0, nb, 0, tid);
    __syncthreads();

    for (int ch = 0; ch < 36; ++ch) {
        int cur = ch & 1;
        if (ch + 1 < 36)
            gemm_fill(AsW[cur ^ 1], BsW[cur ^ 1], data, m0, nb, ch + 1, tid);

        #pragma unroll
        for (int ks = 0; ks < 3; ++ks) {
            uint32_t ka2 = (ks == 2) ? 32u : 0u;
            uint32_t kb2 = (ks == 1) ? 32u : 0u;
            uint32_t bq0[4], bq1[4];
            ldsm4(bq0, bsb[cur] + boff + kb2);                         // cols +0..15
            ldsm4(bq1, bsb[cur] + boff + 16 * RSTRE * 2 + kb2);        // cols +16..31
            uint32_t bf[4][2] = { { bq0[0], bq0[2] }, { bq0[1], bq0[3] },
                                  { bq1[0], bq1[2] }, { bq1[1], bq1[3] } };
            #pragma unroll
            for (int mt = 0; mt < 4; ++mt) {
                uint32_t aq[4];
                ldsm4(aq, asb[cur] + aoff + ka2 + (uint32_t)(mt * 16 * RSTRE * 2));
                #pragma unroll
                for (int nt = 0; nt < 4; ++nt)
                    mma_bf16(acc[mt][nt], aq, bf[nt]);
            }
        }
        __syncthreads();
    }

    // ---- epilogue ----
    #pragma unroll
    for (int mt = 0; mt < 4; ++mt) {
        int r = m0 + warp_m * 64 + mt * 16 + gr;
        #pragma unroll
        for (int nt = 0; nt < 4; ++nt) {
            int c = n0 + warp_n * 32 + nt * 8 + 2 * tq;
            *(float2*)&out[(size_t)r * DIM + c]       = make_float2(acc[mt][nt][0], acc[mt][nt][1]);
            *(float2*)&out[(size_t)(r + 8) * DIM + c] = make_float2(acc[mt][nt][2], acc[mt][nt][3]);
        }
    }
}

// ============================================================
extern "C" void kernel_launch(void* const* d_in, const int* in_sizes, int n_in,
                              void* d_out, int out_size) {
    const float* data = (const float*)d_in[0];   // [4,4096,512]
    const float* Wabs = (const float*)d_in[1];   // [64,512]
    const float* Wm   = (const float*)d_in[2];   // [1024,512]
    float* out = (float*)d_out;                  // [4,4096,512]

    k_norms<<<2048, 256>>>(data);
    k_wc<<<128, 256>>>(Wabs, Wm);
    k_prepB<<<1152, 256>>>(Wm);
    k_scan<<<256, 128>>>(data);
    k_pooled<<<BATCH * NT, 256>>>(data);
    k_gemm_mma<<<dim3(4, 128), 256>>>(data, out);
}